// round 8
// baseline (speedup 1.0000x reference)
#include <cuda_runtime.h>
#include <math.h>
#include <stdint.h>

#define DM 512
#define NROWS 4096      // B*S = B*M = 2*2048
#define HEADS 8
#define DK 64
#define DFF 2048
#define LN_EPS 1e-6f

// ---------------- scratch ----------------
__device__ float g_ln [NROWS * DM];
__device__ float g_q  [NROWS * DM];
__device__ float g_k  [NROWS * DM];
__device__ float g_v  [NROWS * DM];
__device__ float g_att[NROWS * DM];
__device__ float g_res[NROWS * DM];
__device__ float g_ffn[NROWS * DFF];

// ---------------- helpers ----------------
__device__ __forceinline__ uint32_t smaddr(const void* p) {
  return (uint32_t)__cvta_generic_to_shared(p);
}
#define CP16(dst, src) asm volatile("cp.async.cg.shared.global [%0], [%1], 16;\n" :: "r"(dst), "l"(src))
#define CPCOMMIT() asm volatile("cp.async.commit_group;\n")
#define CPWAIT(n)  asm volatile("cp.async.wait_group %0;\n" :: "n"(n))

__device__ __forceinline__ void mma8(float* c, const uint32_t* a, uint32_t b0, uint32_t b1) {
  asm volatile(
      "mma.sync.aligned.m16n8k8.row.col.f32.tf32.tf32.f32 "
      "{%0,%1,%2,%3}, {%4,%5,%6,%7}, {%8,%9}, {%0,%1,%2,%3};\n"
      : "+f"(c[0]), "+f"(c[1]), "+f"(c[2]), "+f"(c[3])
      : "r"(a[0]), "r"(a[1]), "r"(a[2]), "r"(a[3]), "r"(b0), "r"(b1));
}

// ---------------- LayerNorm ----------------
__global__ __launch_bounds__(256) void ln_kernel(
    const float* __restrict__ x, const float* __restrict__ a,
    const float* __restrict__ b, float* __restrict__ out) {
  int row = blockIdx.x;
  int t = threadIdx.x;
  const float* xr = x + (size_t)row * DM;
  float v0 = xr[t], v1 = xr[t + 256];
  float s = v0 + v1, ss = v0 * v0 + v1 * v1;
  #pragma unroll
  for (int o = 16; o; o >>= 1) {
    s  += __shfl_xor_sync(0xffffffffu, s, o);
    ss += __shfl_xor_sync(0xffffffffu, ss, o);
  }
  __shared__ float sh[16];
  int w = t >> 5;
  if ((t & 31) == 0) { sh[w] = s; sh[w + 8] = ss; }
  __syncthreads();
  float ts = 0.f, tss = 0.f;
  #pragma unroll
  for (int i = 0; i < 8; i++) { ts += sh[i]; tss += sh[i + 8]; }
  float mu  = ts * (1.0f / DM);
  float var = (tss - (float)DM * mu * mu) * (1.0f / (DM - 1));  // ddof=1
  float sd  = sqrtf(fmaxf(var, 0.0f));
  float inv = 1.0f / (sd + LN_EPS);
  float* orow = out + (size_t)row * DM;
  orow[t]       = a[t]       * (v0 - mu) * inv + b[t];
  orow[t + 256] = a[t + 256] * (v1 - mu) * inv + b[t + 256];
}

// ---------------- tf32 GEMM, cp.async 3-stage ----------------
// 256 threads, 8 warps (2x4), warp tile 64x32, CTA tile 128x128, BK=32.
// Up to 3 fused weight matrices selected by blockIdx.x / ctiles.
#define STG 3
#define AP 36     // A smem pitch -> bank 4g+tg conflict-free
#define BP 136    // B smem pitch -> bank 8tg+g conflict-free
#define STAGE_F (128 * AP + 32 * BP)   // 8960 floats
#define GSMEM (STG * STAGE_F * 4)      // 107520 B

__global__ __launch_bounds__(256, 2) void gemm_tc(
    const float* __restrict__ A,
    const float* __restrict__ B0, const float* __restrict__ B1, const float* __restrict__ B2,
    const float* __restrict__ bias, const float* __restrict__ resid,
    float* __restrict__ C0, float* __restrict__ C1, float* __restrict__ C2,
    int N, int K, int ctiles, int relu) {
  extern __shared__ float sm[];
  int bx = blockIdx.x;
  int wsel = bx / ctiles;
  int col0 = (bx - wsel * ctiles) * 128;
  const float* B = (wsel == 0) ? B0 : (wsel == 1 ? B1 : B2);
  float* C       = (wsel == 0) ? C0 : (wsel == 1 ? C1 : C2);
  int row0 = blockIdx.y * 128;
  int tid = threadIdx.x, lane = tid & 31, wid = tid >> 5;
  int g = lane >> 2, tg = lane & 3;
  int wm = (wid >> 2) * 64, wn = (wid & 3) * 32;

  float acc[4][4][4];
  #pragma unroll
  for (int i = 0; i < 4; i++)
    #pragma unroll
    for (int j = 0; j < 4; j++)
      #pragma unroll
      for (int k = 0; k < 4; k++) acc[i][j][k] = 0.f;

  auto issue = [&](int s, int kt2) {
    float* As = sm + s * STAGE_F;
    float* Bs = As + 128 * AP;
    int k0 = kt2 * 32;
    #pragma unroll
    for (int i = 0; i < 4; i++) {
      int ch = i * 256 + tid;
      int r = ch >> 3, c = (ch & 7) * 4;
      CP16(smaddr(As + r * AP + c), A + (size_t)(row0 + r) * K + k0 + c);
    }
    #pragma unroll
    for (int i = 0; i < 4; i++) {
      int ch = i * 256 + tid;
      int kr = ch >> 5, c = (ch & 31) * 4;
      CP16(smaddr(Bs + kr * BP + c), B + (size_t)(k0 + kr) * N + col0 + c);
    }
  };

  int nk = K >> 5;
  #pragma unroll
  for (int s = 0; s < STG - 1; s++) {
    if (s < nk) issue(s, s);
    CPCOMMIT();
  }

  for (int kt = 0; kt < nk; kt++) {
    CPWAIT(STG - 2);
    __syncthreads();
    int nx = kt + STG - 1;
    if (nx < nk) issue(nx % STG, nx);
    CPCOMMIT();

    const float* As = sm + (kt % STG) * STAGE_F;
    const float* Bs = As + 128 * AP;
    #pragma unroll
    for (int ks = 0; ks < 4; ks++) {
      int k0 = ks * 8;
      uint32_t af[4][4];
      #pragma unroll
      for (int mt = 0; mt < 4; mt++) {
        const float* ap = As + (wm + mt * 16 + g) * AP + k0 + tg;
        af[mt][0] = __float_as_uint(ap[0]);
        af[mt][1] = __float_as_uint(ap[8 * AP]);
        af[mt][2] = __float_as_uint(ap[4]);
        af[mt][3] = __float_as_uint(ap[8 * AP + 4]);
      }
      #pragma unroll
      for (int nt = 0; nt < 4; nt++) {
        const float* bp = Bs + (k0 + tg) * BP + wn + nt * 8 + g;
        uint32_t b0 = __float_as_uint(bp[0]);
        uint32_t b1 = __float_as_uint(bp[4 * BP]);
        #pragma unroll
        for (int mt = 0; mt < 4; mt++)
          mma8(acc[mt][nt], af[mt], b0, b1);
      }
    }
  }

  // epilogue
  #pragma unroll
  for (int mt = 0; mt < 4; mt++) {
    int r = row0 + wm + mt * 16 + g;
    #pragma unroll
    for (int nt = 0; nt < 4; nt++) {
      int c = col0 + wn + nt * 8 + 2 * tg;
      float2 v0 = make_float2(acc[mt][nt][0], acc[mt][nt][1]);
      float2 v1 = make_float2(acc[mt][nt][2], acc[mt][nt][3]);
      if (bias) {
        float b0 = bias[c], b1 = bias[c + 1];
        v0.x += b0; v0.y += b1; v1.x += b0; v1.y += b1;
      }
      if (resid) {
        float2 r0v = *(const float2*)(resid + (size_t)r * N + c);
        float2 r1v = *(const float2*)(resid + (size_t)(r + 8) * N + c);
        v0.x += r0v.x; v0.y += r0v.y; v1.x += r1v.x; v1.y += r1v.y;
      }
      if (relu) {
        v0.x = fmaxf(v0.x, 0.f); v0.y = fmaxf(v0.y, 0.f);
        v1.x = fmaxf(v1.x, 0.f); v1.y = fmaxf(v1.y, 0.f);
      }
      *(float2*)(C + (size_t)r * N + c) = v0;
      *(float2*)(C + (size_t)(r + 8) * N + c) = v1;
    }
  }
}

// ---------------- tf32 flash attention, Q-tile 128, warp 32x64 ----------------
// Double-buffered K/V with one cp.async group in flight (prefetch kt+1).
#define QP 68
#define KP 68
#define VP 72
#define PP 68
#define AQ_F (128 * QP)
#define AK_F (64 * KP)
#define AV_F (64 * VP)
#define ASMEM ((AQ_F + 2 * AK_F + 2 * AV_F + 128 * PP) * 4)

__global__ __launch_bounds__(128) void attn_tc(
    const float* __restrict__ Q, const float* __restrict__ K,
    const float* __restrict__ V, float* __restrict__ O, int causal) {
  extern __shared__ float sm[];
  float* Qs  = sm;
  float* Ks0 = Qs + AQ_F;
  float* Vs0 = Ks0 + 2 * AK_F;
  float* Ps  = Vs0 + 2 * AV_F;

  int tid = threadIdx.x, lane = tid & 31, w = tid >> 5;
  int g = lane >> 2, tg = lane & 3;
  int qt = blockIdx.x, h = blockIdx.y, b = blockIdx.z;
  int q0 = qt * 128;

  const float* Qb = Q + ((size_t)b * 2048 + q0) * DM + h * DK;
  const float* Kb = K + ((size_t)b * 2048) * DM + h * DK;
  const float* Vb = V + ((size_t)b * 2048) * DM + h * DK;

  auto issue_kv = [&](int buf, int kt2) {
    float* Ks = Ks0 + buf * AK_F;
    float* Vs = Vs0 + buf * AV_F;
    int k0 = kt2 * 64;
    #pragma unroll
    for (int i = 0; i < 8; i++) {
      int ch = i * 128 + tid;
      int r = ch >> 4, c = (ch & 15) * 4;
      CP16(smaddr(Ks + r * KP + c), Kb + (size_t)(k0 + r) * DM + c);
      CP16(smaddr(Vs + r * VP + c), Vb + (size_t)(k0 + r) * DM + c);
    }
  };

  // load Q (group 0)
  #pragma unroll
  for (int i = 0; i < 16; i++) {
    int ch = i * 128 + tid;
    int r = ch >> 4, c = (ch & 15) * 4;
    CP16(smaddr(Qs + r * QP + c), Qb + (size_t)r * DM + c);
  }
  CPCOMMIT();
  // prefetch KV tile 0 (group 1)
  issue_kv(0, 0);
  CPCOMMIT();

  float m[2][2], l[2][2], oacc[2][8][4];
  #pragma unroll
  for (int mt = 0; mt < 2; mt++) {
    m[mt][0] = -1e30f; m[mt][1] = -1e30f;
    l[mt][0] = 0.f; l[mt][1] = 0.f;
    #pragma unroll
    for (int nt = 0; nt < 8; nt++)
      #pragma unroll
      for (int j = 0; j < 4; j++) oacc[mt][nt][j] = 0.f;
  }

  int ntiles = causal ? (2 * qt + 2) : 32;
  const float scale = 0.125f;  // 1/sqrt(64)
  int rb = q0 + w * 32;

  for (int kt = 0; kt < ntiles; kt++) {
    int k0 = kt * 64;
    __syncthreads();  // all warps done reading buf[(kt+1)&1] from iter kt-1
    bool pf = (kt + 1 < ntiles);
    if (pf) { issue_kv((kt + 1) & 1, kt + 1); CPCOMMIT(); }
    if (pf) { CPWAIT(1); } else { CPWAIT(0); }
    __syncthreads();

    const float* Ks = Ks0 + (kt & 1) * AK_F;
    const float* Vs = Vs0 + (kt & 1) * AV_F;

    // S = Q @ K^T  (warp: 32 rows x 64 cols)
    float sacc[2][8][4];
    #pragma unroll
    for (int mt = 0; mt < 2; mt++)
      #pragma unroll
      for (int nt = 0; nt < 8; nt++)
        #pragma unroll
        for (int j = 0; j < 4; j++) sacc[mt][nt][j] = 0.f;

    #pragma unroll
    for (int ks = 0; ks < 8; ks++) {
      int d0 = ks * 8;
      uint32_t af[2][4];
      #pragma unroll
      for (int mt = 0; mt < 2; mt++) {
        const float* ap = Qs + (w * 32 + mt * 16 + g) * QP + d0 + tg;
        af[mt][0] = __float_as_uint(ap[0]);
        af[mt][1] = __float_as_uint(ap[8 * QP]);
        af[mt][2] = __float_as_uint(ap[4]);
        af[mt][3] = __float_as_uint(ap[8 * QP + 4]);
      }
      #pragma unroll
      for (int nt = 0; nt < 8; nt++) {
        const float* kp = Ks + (nt * 8 + g) * KP + d0 + tg;
        uint32_t b0 = __float_as_uint(kp[0]);
        uint32_t b1 = __float_as_uint(kp[4]);
        #pragma unroll
        for (int mt = 0; mt < 2; mt++)
          mma8(sacc[mt][nt], af[mt], b0, b1);
      }
    }

    bool needm = (causal != 0) && (kt >= 2 * qt);
    #pragma unroll
    for (int mt = 0; mt < 2; mt++) {
      int r0 = rb + mt * 16 + g, r1 = r0 + 8;
      #pragma unroll
      for (int nt = 0; nt < 8; nt++) {
        int c = k0 + nt * 8 + 2 * tg;
        float s0 = sacc[mt][nt][0] * scale, s1 = sacc[mt][nt][1] * scale;
        float s2 = sacc[mt][nt][2] * scale, s3 = sacc[mt][nt][3] * scale;
        if (needm) {
          if (c > r0)     s0 = -1e30f;
          if (c + 1 > r0) s1 = -1e30f;
          if (c > r1)     s2 = -1e30f;
          if (c + 1 > r1) s3 = -1e30f;
        }
        sacc[mt][nt][0] = s0; sacc[mt][nt][1] = s1;
        sacc[mt][nt][2] = s2; sacc[mt][nt][3] = s3;
      }

      float mx0 = -1e30f, mx1 = -1e30f;
      #pragma unroll
      for (int nt = 0; nt < 8; nt++) {
        mx0 = fmaxf(mx0, fmaxf(sacc[mt][nt][0], sacc[mt][nt][1]));
        mx1 = fmaxf(mx1, fmaxf(sacc[mt][nt][2], sacc[mt][nt][3]));
      }
      mx0 = fmaxf(mx0, __shfl_xor_sync(0xffffffffu, mx0, 1));
      mx0 = fmaxf(mx0, __shfl_xor_sync(0xffffffffu, mx0, 2));
      mx1 = fmaxf(mx1, __shfl_xor_sync(0xffffffffu, mx1, 1));
      mx1 = fmaxf(mx1, __shfl_xor_sync(0xffffffffu, mx1, 2));
      float mn0 = fmaxf(m[mt][0], mx0), mn1 = fmaxf(m[mt][1], mx1);
      float al0 = __expf(m[mt][0] - mn0), al1 = __expf(m[mt][1] - mn1);
      m[mt][0] = mn0; m[mt][1] = mn1;
      float sum0 = 0.f, sum1 = 0.f;
      #pragma unroll
      for (int nt = 0; nt < 8; nt++) {
        float p0 = __expf(sacc[mt][nt][0] - mn0);
        float p1 = __expf(sacc[mt][nt][1] - mn0);
        float p2 = __expf(sacc[mt][nt][2] - mn1);
        float p3 = __expf(sacc[mt][nt][3] - mn1);
        sacc[mt][nt][0] = p0; sacc[mt][nt][1] = p1;
        sacc[mt][nt][2] = p2; sacc[mt][nt][3] = p3;
        sum0 += p0 + p1; sum1 += p2 + p3;
      }
      sum0 += __shfl_xor_sync(0xffffffffu, sum0, 1);
      sum0 += __shfl_xor_sync(0xffffffffu, sum0, 2);
      sum1 += __shfl_xor_sync(0xffffffffu, sum1, 1);
      sum1 += __shfl_xor_sync(0xffffffffu, sum1, 2);
      l[mt][0] = l[mt][0] * al0 + sum0;
      l[mt][1] = l[mt][1] * al1 + sum1;
      #pragma unroll
      for (int nt = 0; nt < 8; nt++) {
        oacc[mt][nt][0] *= al0; oacc[mt][nt][1] *= al0;
        oacc[mt][nt][2] *= al1; oacc[mt][nt][3] *= al1;
      }

      int pb = (w * 32 + mt * 16 + g) * PP;
      #pragma unroll
      for (int nt = 0; nt < 8; nt++) {
        int c = nt * 8 + 2 * tg;
        Ps[pb + c]              = sacc[mt][nt][0];
        Ps[pb + c + 1]          = sacc[mt][nt][1];
        Ps[pb + 8 * PP + c]     = sacc[mt][nt][2];
        Ps[pb + 8 * PP + c + 1] = sacc[mt][nt][3];
      }
    }
    __syncwarp();

    // O += P @ V
    #pragma unroll
    for (int ks = 0; ks < 8; ks++) {
      int kk = ks * 8;
      uint32_t af[2][4];
      #pragma unroll
      for (int mt = 0; mt < 2; mt++) {
        const float* ap = Ps + (w * 32 + mt * 16 + g) * PP + kk + tg;
        af[mt][0] = __float_as_uint(ap[0]);
        af[mt][1] = __float_as_uint(ap[8 * PP]);
        af[mt][2] = __float_as_uint(ap[4]);
        af[mt][3] = __float_as_uint(ap[8 * PP + 4]);
      }
      #pragma unroll
      for (int nt = 0; nt < 8; nt++) {
        const float* vp = Vs + (kk + tg) * VP + nt * 8 + g;
        uint32_t b0 = __float_as_uint(vp[0]);
        uint32_t b1 = __float_as_uint(vp[4 * VP]);
        #pragma unroll
        for (int mt = 0; mt < 2; mt++)
          mma8(oacc[mt][nt], af[mt], b0, b1);
      }
    }
  }

  #pragma unroll
  for (int mt = 0; mt < 2; mt++) {
    float inv0 = 1.0f / l[mt][0], inv1 = 1.0f / l[mt][1];
    size_t r = (size_t)b * 2048 + q0 + w * 32 + mt * 16 + g;
    #pragma unroll
    for (int nt = 0; nt < 8; nt++) {
      int c = h * DK + nt * 8 + 2 * tg;
      float2 v0 = make_float2(oacc[mt][nt][0] * inv0, oacc[mt][nt][1] * inv0);
      float2 v1 = make_float2(oacc[mt][nt][2] * inv1, oacc[mt][nt][3] * inv1);
      *(float2*)(O + r * DM + c) = v0;
      *(float2*)(O + (r + 8) * DM + c) = v1;
    }
  }
}

// ---------------- launch ----------------
extern "C" void kernel_launch(void* const* d_in, const int* in_sizes, int n_in,
                              void* d_out, int out_size) {
  const float* x    = (const float*)d_in[0];
  const float* mem  = (const float*)d_in[1];
  const float* ln1a = (const float*)d_in[2];
  const float* ln1b = (const float*)d_in[3];
  const float* ln2a = (const float*)d_in[4];
  const float* ln2b = (const float*)d_in[5];
  const float* ln3a = (const float*)d_in[6];
  const float* ln3b = (const float*)d_in[7];
  const float* a1wq = (const float*)d_in[8];
  const float* a1wk = (const float*)d_in[9];
  const float* a1wv = (const float*)d_in[10];
  const float* a1wo = (const float*)d_in[11];
  const float* a1bo = (const float*)d_in[12];
  const float* a2wq = (const float*)d_in[13];
  const float* a2wk = (const float*)d_in[14];
  const float* a2wv = (const float*)d_in[15];
  const float* a2wo = (const float*)d_in[16];
  const float* a2bo = (const float*)d_in[17];
  const float* fw1  = (const float*)d_in[18];
  const float* fb1  = (const float*)d_in[19];
  const float* fw2  = (const float*)d_in[20];
  const float* fb2  = (const float*)d_in[21];
  float* out = (float*)d_out;

  float *p_ln, *p_q, *p_k, *p_v, *p_att, *p_res, *p_ffn;
  cudaGetSymbolAddress((void**)&p_ln,  g_ln);
  cudaGetSymbolAddress((void**)&p_q,   g_q);
  cudaGetSymbolAddress((void**)&p_k,   g_k);
  cudaGetSymbolAddress((void**)&p_v,   g_v);
  cudaGetSymbolAddress((void**)&p_att, g_att);
  cudaGetSymbolAddress((void**)&p_res, g_res);
  cudaGetSymbolAddress((void**)&p_ffn, g_ffn);

  cudaFuncSetAttribute(gemm_tc, cudaFuncAttributeMaxDynamicSharedMemorySize, GSMEM);
  cudaFuncSetAttribute(attn_tc, cudaFuncAttributeMaxDynamicSharedMemorySize, ASMEM);

  dim3 gQKV(12, 32);  // 3 weights x 4 col tiles
  dim3 gKV(8, 32);    // 2 weights x 4 col tiles
  dim3 gP(4, 32);     // N=512 single
  dim3 gF1(16, 32);   // N=2048 single
  dim3 gA(16, HEADS, 2);

  // --- self-attention block ---
  ln_kernel<<<NROWS, 256>>>(x, ln1a, ln1b, p_ln);
  gemm_tc<<<gQKV, 256, GSMEM>>>(p_ln, a1wq, a1wk, a1wv, nullptr, nullptr,
                                p_q, p_k, p_v, DM, DM, 4, 0);
  attn_tc<<<gA, 128, ASMEM>>>(p_q, p_k, p_v, p_att, 1);
  gemm_tc<<<gP, 256, GSMEM>>>(p_att, a1wo, a1wo, a1wo, a1bo, x,
                              p_res, p_res, p_res, DM, DM, 4, 0);

  // --- cross-attention block ---
  ln_kernel<<<NROWS, 256>>>(p_res, ln2a, ln2b, p_ln);
  gemm_tc<<<gP, 256, GSMEM>>>(p_ln, a2wq, a2wq, a2wq, nullptr, nullptr,
                              p_q, p_q, p_q, DM, DM, 4, 0);
  gemm_tc<<<gKV, 256, GSMEM>>>(mem, a2wk, a2wv, a2wv, nullptr, nullptr,
                               p_k, p_v, p_v, DM, DM, 4, 0);
  attn_tc<<<gA, 128, ASMEM>>>(p_q, p_k, p_v, p_att, 0);
  gemm_tc<<<gP, 256, GSMEM>>>(p_att, a2wo, a2wo, a2wo, a2bo, p_res,
                              p_res, p_res, p_res, DM, DM, 4, 0);

  // --- FFN block ---
  ln_kernel<<<NROWS, 256>>>(p_res, ln3a, ln3b, p_ln);
  gemm_tc<<<gF1, 256, GSMEM>>>(p_ln, fw1, fw1, fw1, fb1, nullptr,
                               p_ffn, p_ffn, p_ffn, DFF, DM, 16, 1);
  gemm_tc<<<gP, 256, GSMEM>>>(p_ffn, fw2, fw2, fw2, fb2, p_res,
                              out, out, out, DM, DFF, 4, 0);
}

// round 9
// speedup vs baseline: 1.5474x; 1.5474x over previous
#include <cuda_runtime.h>
#include <cuda_fp16.h>
#include <math.h>
#include <stdint.h>

#define DM 512
#define NROWS 4096
#define HEADS 8
#define DK 64
#define DFF 2048
#define LN_EPS 1e-6f

// ---------------- scratch ----------------
__device__ float  g_res[NROWS * DM];
__device__ __half h_ln [NROWS * DM];
__device__ __half h_mem[NROWS * DM];
__device__ __half h_q  [NROWS * DM];
__device__ __half h_k  [NROWS * DM];
__device__ __half h_v  [NROWS * DM];
__device__ __half h_att[NROWS * DM];
__device__ __half h_ffn[NROWS * DFF];
__device__ __half h_w0[DM * DM];  // a1wq^T
__device__ __half h_w1[DM * DM];  // a1wk^T
__device__ __half h_w2[DM * DM];  // a1wv^T
__device__ __half h_w3[DM * DM];  // a1wo^T
__device__ __half h_w4[DM * DM];  // a2wq^T
__device__ __half h_w5[DM * DM];  // a2wk^T
__device__ __half h_w6[DM * DM];  // a2wv^T
__device__ __half h_w7[DM * DM];  // a2wo^T
__device__ __half h_wf1[DM * DFF]; // fw1^T [2048][512]
__device__ __half h_wf2[DM * DFF]; // fw2^T [512][2048]

// ---------------- helpers ----------------
__device__ __forceinline__ uint32_t smaddr(const void* p) {
  return (uint32_t)__cvta_generic_to_shared(p);
}
#define CP16(dst, src) asm volatile("cp.async.cg.shared.global [%0], [%1], 16;\n" :: "r"(dst), "l"(src))
#define CPCOMMIT() asm volatile("cp.async.commit_group;\n")
#define CPWAIT(n)  asm volatile("cp.async.wait_group %0;\n" :: "n"(n))

__device__ __forceinline__ void mma16(float* c, const uint32_t* a, uint32_t b0, uint32_t b1) {
  asm volatile(
      "mma.sync.aligned.m16n8k16.row.col.f32.f16.f16.f32 "
      "{%0,%1,%2,%3}, {%4,%5,%6,%7}, {%8,%9}, {%0,%1,%2,%3};\n"
      : "+f"(c[0]), "+f"(c[1]), "+f"(c[2]), "+f"(c[3])
      : "r"(a[0]), "r"(a[1]), "r"(a[2]), "r"(a[3]), "r"(b0), "r"(b1));
}
__device__ __forceinline__ uint32_t ldh32(const __half* p) {
  return *reinterpret_cast<const uint32_t*>(p);
}

// ---------------- converts ----------------
__global__ __launch_bounds__(256) void cvt_kernel(const float* __restrict__ in,
                                                  __half* __restrict__ out) {
  int i = blockIdx.x * 256 + threadIdx.x;
  float4 v = reinterpret_cast<const float4*>(in)[i];
  reinterpret_cast<__half2*>(out)[2 * i]     = __floats2half2_rn(v.x, v.y);
  reinterpret_cast<__half2*>(out)[2 * i + 1] = __floats2half2_rn(v.z, v.w);
}

// transpose-convert: W[K][N] fp32 -> WT[N][K] fp16
__global__ __launch_bounds__(256) void wcvt_kernel(const float* __restrict__ W,
                                                   __half* __restrict__ WT,
                                                   int K, int N) {
  __shared__ float t[32][33];
  int n0 = blockIdx.x * 32, k0 = blockIdx.y * 32;
  int tx = threadIdx.x & 31, ty = threadIdx.x >> 5;  // 32 x 8
  #pragma unroll
  for (int i = 0; i < 4; i++)
    t[ty + 8 * i][tx] = W[(size_t)(k0 + ty + 8 * i) * N + n0 + tx];
  __syncthreads();
  #pragma unroll
  for (int i = 0; i < 4; i++)
    WT[(size_t)(n0 + ty + 8 * i) * K + k0 + tx] = __float2half_rn(t[tx][ty + 8 * i]);
}

// 8x fused 512x512 transpose-convert, z selects weight
__global__ __launch_bounds__(256) void wcvt8_kernel(
    const float* w0, const float* w1, const float* w2, const float* w3,
    const float* w4, const float* w5, const float* w6, const float* w7,
    __half* o0, __half* o1, __half* o2, __half* o3,
    __half* o4, __half* o5, __half* o6, __half* o7) {
  const float* W; __half* WT;
  switch (blockIdx.z) {
    case 0: W = w0; WT = o0; break;  case 1: W = w1; WT = o1; break;
    case 2: W = w2; WT = o2; break;  case 3: W = w3; WT = o3; break;
    case 4: W = w4; WT = o4; break;  case 5: W = w5; WT = o5; break;
    case 6: W = w6; WT = o6; break;  default: W = w7; WT = o7; break;
  }
  __shared__ float t[32][33];
  int n0 = blockIdx.x * 32, k0 = blockIdx.y * 32;
  int tx = threadIdx.x & 31, ty = threadIdx.x >> 5;
  #pragma unroll
  for (int i = 0; i < 4; i++)
    t[ty + 8 * i][tx] = W[(size_t)(k0 + ty + 8 * i) * DM + n0 + tx];
  __syncthreads();
  #pragma unroll
  for (int i = 0; i < 4; i++)
    WT[(size_t)(n0 + ty + 8 * i) * DM + k0 + tx] = __float2half_rn(t[tx][ty + 8 * i]);
}

// ---------------- LayerNorm (fp32 in, fp16 out) ----------------
__global__ __launch_bounds__(256) void ln_kernel(
    const float* __restrict__ x, const float* __restrict__ a,
    const float* __restrict__ b, __half* __restrict__ out) {
  int row = blockIdx.x;
  int t = threadIdx.x;
  const float* xr = x + (size_t)row * DM;
  float v0 = xr[t], v1 = xr[t + 256];
  float s = v0 + v1, ss = v0 * v0 + v1 * v1;
  #pragma unroll
  for (int o = 16; o; o >>= 1) {
    s  += __shfl_xor_sync(0xffffffffu, s, o);
    ss += __shfl_xor_sync(0xffffffffu, ss, o);
  }
  __shared__ float sh[16];
  int w = t >> 5;
  if ((t & 31) == 0) { sh[w] = s; sh[w + 8] = ss; }
  __syncthreads();
  float ts = 0.f, tss = 0.f;
  #pragma unroll
  for (int i = 0; i < 8; i++) { ts += sh[i]; tss += sh[i + 8]; }
  float mu  = ts * (1.0f / DM);
  float var = (tss - (float)DM * mu * mu) * (1.0f / (DM - 1));  // ddof=1
  float sd  = sqrtf(fmaxf(var, 0.0f));
  float inv = 1.0f / (sd + LN_EPS);
  __half* orow = out + (size_t)row * DM;
  orow[t]       = __float2half_rn(a[t]       * (v0 - mu) * inv + b[t]);
  orow[t + 256] = __float2half_rn(a[t + 256] * (v1 - mu) * inv + b[t + 256]);
}

// ---------------- fp16 GEMM, cp.async 3-stage ----------------
// A [M][K] fp16, B = W^T [N][K] fp16. CTA 128x128, BK=32, 8 warps (2x4),
// warp 64x32. fp32 accum. Output fp32 (bias/resid/relu) or fp16.
#define STG 3
#define APH 40                     // halves pitch (32 + 8 pad) -> conflict-free
#define STAGE_H (2 * 128 * APH)    // A + B halves per stage = 10240
#define GSMEM (STG * STAGE_H * 2)  // bytes = 61440

__global__ __launch_bounds__(256, 2) void gemm_h(
    const __half* __restrict__ A,
    const __half* B0, const __half* B1, const __half* B2,
    const float* __restrict__ bias, const float* __restrict__ resid,
    void* C0, void* C1, void* C2,
    int N, int K, int ctiles, int relu, int out16) {
  extern __shared__ __half smh[];
  int bx = blockIdx.x;
  int wsel = bx / ctiles;
  int col0 = (bx - wsel * ctiles) * 128;
  const __half* B = (wsel == 0) ? B0 : (wsel == 1 ? B1 : B2);
  void* C        = (wsel == 0) ? C0 : (wsel == 1 ? C1 : C2);
  int row0 = blockIdx.y * 128;
  int tid = threadIdx.x, lane = tid & 31, wid = tid >> 5;
  int g = lane >> 2, tg = lane & 3;
  int wm = (wid >> 2) * 64, wn = (wid & 3) * 32;

  float acc[4][4][4];
  #pragma unroll
  for (int i = 0; i < 4; i++)
    #pragma unroll
    for (int j = 0; j < 4; j++)
      #pragma unroll
      for (int k = 0; k < 4; k++) acc[i][j][k] = 0.f;

  auto issue = [&](int s, int kt2) {
    __half* As = smh + s * STAGE_H;
    __half* Bs = As + 128 * APH;
    int k0 = kt2 * 32;
    #pragma unroll
    for (int i = 0; i < 2; i++) {
      int ch = i * 256 + tid;
      int r = ch >> 2, c = (ch & 3) * 8;
      CP16(smaddr(As + r * APH + c), A + (size_t)(row0 + r) * K + k0 + c);
      CP16(smaddr(Bs + r * APH + c), B + (size_t)(col0 + r) * K + k0 + c);
    }
  };

  int nk = K >> 5;
  #pragma unroll
  for (int s = 0; s < STG - 1; s++) {
    if (s < nk) issue(s, s);
    CPCOMMIT();
  }

  for (int kt = 0; kt < nk; kt++) {
    CPWAIT(STG - 2);
    __syncthreads();
    int nx = kt + STG - 1;
    if (nx < nk) issue(nx % STG, nx);
    CPCOMMIT();

    const __half* As = smh + (kt % STG) * STAGE_H;
    const __half* Bs = As + 128 * APH;
    #pragma unroll
    for (int ks = 0; ks < 2; ks++) {
      int k0 = ks * 16;
      uint32_t af[4][4];
      #pragma unroll
      for (int mt = 0; mt < 4; mt++) {
        const __half* ap = As + (wm + mt * 16 + g) * APH + k0 + 2 * tg;
        af[mt][0] = ldh32(ap);
        af[mt][1] = ldh32(ap + 8 * APH);
        af[mt][2] = ldh32(ap + 8);
        af[mt][3] = ldh32(ap + 8 * APH + 8);
      }
      #pragma unroll
      for (int nt = 0; nt < 4; nt++) {
        const __half* bp = Bs + (wn + nt * 8 + g) * APH + k0 + 2 * tg;
        uint32_t b0 = ldh32(bp);
        uint32_t b1 = ldh32(bp + 8);
        #pragma unroll
        for (int mt = 0; mt < 4; mt++)
          mma16(acc[mt][nt], af[mt], b0, b1);
      }
    }
  }

  // epilogue
  #pragma unroll
  for (int mt = 0; mt < 4; mt++) {
    int r = row0 + wm + mt * 16 + g;
    #pragma unroll
    for (int nt = 0; nt < 4; nt++) {
      int c = col0 + wn + nt * 8 + 2 * tg;
      float2 v0 = make_float2(acc[mt][nt][0], acc[mt][nt][1]);
      float2 v1 = make_float2(acc[mt][nt][2], acc[mt][nt][3]);
      if (bias) {
        float b0 = bias[c], b1 = bias[c + 1];
        v0.x += b0; v0.y += b1; v1.x += b0; v1.y += b1;
      }
      if (resid) {
        float2 r0v = *(const float2*)(resid + (size_t)r * N + c);
        float2 r1v = *(const float2*)(resid + (size_t)(r + 8) * N + c);
        v0.x += r0v.x; v0.y += r0v.y; v1.x += r1v.x; v1.y += r1v.y;
      }
      if (relu) {
        v0.x = fmaxf(v0.x, 0.f); v0.y = fmaxf(v0.y, 0.f);
        v1.x = fmaxf(v1.x, 0.f); v1.y = fmaxf(v1.y, 0.f);
      }
      if (out16) {
        __half* Ch = (__half*)C;
        *reinterpret_cast<__half2*>(Ch + (size_t)r * N + c)       = __floats2half2_rn(v0.x, v0.y);
        *reinterpret_cast<__half2*>(Ch + (size_t)(r + 8) * N + c) = __floats2half2_rn(v1.x, v1.y);
      } else {
        float* Cf = (float*)C;
        *(float2*)(Cf + (size_t)r * N + c) = v0;
        *(float2*)(Cf + (size_t)(r + 8) * N + c) = v1;
      }
    }
  }
}

// ---------------- fp16 flash attention ----------------
// Q-tile 128, K/V tiles 64 (double-buffered cp.async), 4 warps, warp 32 q-rows.
#define QPH 72
#define AQ_H (128 * QPH)
#define AK_H (64 * QPH)
#define ASMEM ((AQ_H + 2 * AK_H + 2 * AK_H + 128 * QPH) * 2)

__global__ __launch_bounds__(128) void attn_h(
    const __half* __restrict__ Q, const __half* __restrict__ K,
    const __half* __restrict__ V, __half* __restrict__ O, int causal) {
  extern __shared__ __half smh[];
  __half* Qs  = smh;
  __half* Ks0 = Qs + AQ_H;
  __half* Vs0 = Ks0 + 2 * AK_H;
  __half* Ps  = Vs0 + 2 * AK_H;

  int tid = threadIdx.x, lane = tid & 31, w = tid >> 5;
  int g = lane >> 2, tg = lane & 3;
  int qt = blockIdx.x, h = blockIdx.y, b = blockIdx.z;
  int q0 = qt * 128;

  const __half* Qb = Q + ((size_t)b * 2048 + q0) * DM + h * DK;
  const __half* Kb = K + ((size_t)b * 2048) * DM + h * DK;
  const __half* Vb = V + ((size_t)b * 2048) * DM + h * DK;

  auto issue_kv = [&](int buf, int kt2) {
    __half* Ks = Ks0 + buf * AK_H;
    __half* Vs = Vs0 + buf * AK_H;
    int k0 = kt2 * 64;
    #pragma unroll
    for (int i = 0; i < 4; i++) {
      int ch = i * 128 + tid;
      int r = ch >> 3, c = (ch & 7) * 8;
      CP16(smaddr(Ks + r * QPH + c), Kb + (size_t)(k0 + r) * DM + c);
      CP16(smaddr(Vs + r * QPH + c), Vb + (size_t)(k0 + r) * DM + c);
    }
  };

  // load Q (group 0)
  #pragma unroll
  for (int i = 0; i < 8; i++) {
    int ch = i * 128 + tid;
    int r = ch >> 3, c = (ch & 7) * 8;
    CP16(smaddr(Qs + r * QPH + c), Qb + (size_t)r * DM + c);
  }
  CPCOMMIT();
  issue_kv(0, 0);
  CPCOMMIT();

  float m[2][2], l[2][2], oacc[2][8][4];
  #pragma unroll
  for (int mt = 0; mt < 2; mt++) {
    m[mt][0] = -1e30f; m[mt][1] = -1e30f;
    l[mt][0] = 0.f; l[mt][1] = 0.f;
    #pragma unroll
    for (int nt = 0; nt < 8; nt++)
      #pragma unroll
      for (int j = 0; j < 4; j++) oacc[mt][nt][j] = 0.f;
  }

  int ntiles = causal ? (2 * qt + 2) : 32;
  const float scale = 0.125f;
  int rb = q0 + w * 32;

  for (int kt = 0; kt < ntiles; kt++) {
    int k0 = kt * 64;
    __syncthreads();
    bool pf = (kt + 1 < ntiles);
    if (pf) { issue_kv((kt + 1) & 1, kt + 1); CPCOMMIT(); }
    if (pf) { CPWAIT(1); } else { CPWAIT(0); }
    __syncthreads();

    const __half* Ks = Ks0 + (kt & 1) * AK_H;
    const __half* Vs = Vs0 + (kt & 1) * AK_H;

    // S = Q @ K^T  (warp: 32 rows x 64 keys), k = d (4 steps of 16)
    float sacc[2][8][4];
    #pragma unroll
    for (int mt = 0; mt < 2; mt++)
      #pragma unroll
      for (int nt = 0; nt < 8; nt++)
        #pragma unroll
        for (int j = 0; j < 4; j++) sacc[mt][nt][j] = 0.f;

    #pragma unroll
    for (int ks = 0; ks < 4; ks++) {
      int d0 = ks * 16;
      uint32_t af[2][4];
      #pragma unroll
      for (int mt = 0; mt < 2; mt++) {
        const __half* ap = Qs + (w * 32 + mt * 16 + g) * QPH + d0 + 2 * tg;
        af[mt][0] = ldh32(ap);
        af[mt][1] = ldh32(ap + 8 * QPH);
        af[mt][2] = ldh32(ap + 8);
        af[mt][3] = ldh32(ap + 8 * QPH + 8);
      }
      #pragma unroll
      for (int nt = 0; nt < 8; nt++) {
        const __half* kp = Ks + (nt * 8 + g) * QPH + d0 + 2 * tg;
        uint32_t b0 = ldh32(kp);
        uint32_t b1 = ldh32(kp + 8);
        #pragma unroll
        for (int mt = 0; mt < 2; mt++)
          mma16(sacc[mt][nt], af[mt], b0, b1);
      }
    }

    bool needm = (causal != 0) && (kt >= 2 * qt);
    #pragma unroll
    for (int mt = 0; mt < 2; mt++) {
      int r0 = rb + mt * 16 + g, r1 = r0 + 8;
      #pragma unroll
      for (int nt = 0; nt < 8; nt++) {
        int c = k0 + nt * 8 + 2 * tg;
        float s0 = sacc[mt][nt][0] * scale, s1 = sacc[mt][nt][1] * scale;
        float s2 = sacc[mt][nt][2] * scale, s3 = sacc[mt][nt][3] * scale;
        if (needm) {
          if (c > r0)     s0 = -1e30f;
          if (c + 1 > r0) s1 = -1e30f;
          if (c > r1)     s2 = -1e30f;
          if (c + 1 > r1) s3 = -1e30f;
        }
        sacc[mt][nt][0] = s0; sacc[mt][nt][1] = s1;
        sacc[mt][nt][2] = s2; sacc[mt][nt][3] = s3;
      }

      float mx0 = -1e30f, mx1 = -1e30f;
      #pragma unroll
      for (int nt = 0; nt < 8; nt++) {
        mx0 = fmaxf(mx0, fmaxf(sacc[mt][nt][0], sacc[mt][nt][1]));
        mx1 = fmaxf(mx1, fmaxf(sacc[mt][nt][2], sacc[mt][nt][3]));
      }
      mx0 = fmaxf(mx0, __shfl_xor_sync(0xffffffffu, mx0, 1));
      mx0 = fmaxf(mx0, __shfl_xor_sync(0xffffffffu, mx0, 2));
      mx1 = fmaxf(mx1, __shfl_xor_sync(0xffffffffu, mx1, 1));
      mx1 = fmaxf(mx1, __shfl_xor_sync(0xffffffffu, mx1, 2));
      float mn0 = fmaxf(m[mt][0], mx0), mn1 = fmaxf(m[mt][1], mx1);
      float al0 = __expf(m[mt][0] - mn0), al1 = __expf(m[mt][1] - mn1);
      m[mt][0] = mn0; m[mt][1] = mn1;
      float sum0 = 0.f, sum1 = 0.f;
      #pragma unroll
      for (int nt = 0; nt < 8; nt++) {
        float p0 = __expf(sacc[mt][nt][0] - mn0);
        float p1 = __expf(sacc[mt][nt][1] - mn0);
        float p2 = __expf(sacc[mt][nt][2] - mn1);
        float p3 = __expf(sacc[mt][nt][3] - mn1);
        sacc[mt][nt][0] = p0; sacc[mt][nt][1] = p1;
        sacc[mt][nt][2] = p2; sacc[mt][nt][3] = p3;
        sum0 += p0 + p1; sum1 += p2 + p3;
      }
      sum0 += __shfl_xor_sync(0xffffffffu, sum0, 1);
      sum0 += __shfl_xor_sync(0xffffffffu, sum0, 2);
      sum1 += __shfl_xor_sync(0xffffffffu, sum1, 1);
      sum1 += __shfl_xor_sync(0xffffffffu, sum1, 2);
      l[mt][0] = l[mt][0] * al0 + sum0;
      l[mt][1] = l[mt][1] * al1 + sum1;
      #pragma unroll
      for (int nt = 0; nt < 8; nt++) {
        oacc[mt][nt][0] *= al0; oacc[mt][nt][1] *= al0;
        oacc[mt][nt][2] *= al1; oacc[mt][nt][3] *= al1;
      }

      // store P (fp16) to per-warp smem region
      __half* pb = Ps + (w * 32 + mt * 16 + g) * QPH;
      #pragma unroll
      for (int nt = 0; nt < 8; nt++) {
        int c = nt * 8 + 2 * tg;
        *reinterpret_cast<__half2*>(pb + c)           = __floats2half2_rn(sacc[mt][nt][0], sacc[mt][nt][1]);
        *reinterpret_cast<__half2*>(pb + 8 * QPH + c) = __floats2half2_rn(sacc[mt][nt][2], sacc[mt][nt][3]);
      }
    }
    __syncwarp();

    // O += P @ V   (k = keys, 4 steps of 16; V via ldmatrix.trans)
    #pragma unroll
    for (int ks = 0; ks < 4; ks++) {
      int kk = ks * 16;
      uint32_t af[2][4];
      #pragma unroll
      for (int mt = 0; mt < 2; mt++) {
        const __half* ap = Ps + (w * 32 + mt * 16 + g) * QPH + kk + 2 * tg;
        af[mt][0] = ldh32(ap);
        af[mt][1] = ldh32(ap + 8 * QPH);
        af[mt][2] = ldh32(ap + 8);
        af[mt][3] = ldh32(ap + 8 * QPH + 8);
      }
      #pragma unroll
      for (int ntp = 0; ntp < 4; ntp++) {
        // ldmatrix.x4.trans over V[key][d]: 16 keys x 16 d
        int j = lane >> 3, r = lane & 7;
        const __half* va = Vs + (kk + (j & 1) * 8 + r) * QPH + ntp * 16 + (j >> 1) * 8;
        uint32_t r0, r1, r2, r3;
        asm volatile(
            "ldmatrix.sync.aligned.m8n8.x4.trans.shared.b16 {%0,%1,%2,%3}, [%4];\n"
            : "=r"(r0), "=r"(r1), "=r"(r2), "=r"(r3)
            : "r"(smaddr(va)));
        #pragma unroll
        for (int mt = 0; mt < 2; mt++) {
          mma16(oacc[mt][2 * ntp],     af[mt], r0, r1);
          mma16(oacc[mt][2 * ntp + 1], af[mt], r2, r3);
        }
      }
    }
  }

  #pragma unroll
  for (int mt = 0; mt < 2; mt++) {
    float inv0 = 1.0f / l[mt][0], inv1 = 1.0f / l[mt][1];
    size_t r = (size_t)b * 2048 + q0 + w * 32 + mt * 16 + g;
    #pragma unroll
    for (int nt = 0; nt < 8; nt++) {
      int c = h * DK + nt * 8 + 2 * tg;
      *reinterpret_cast<__half2*>(O + r * DM + c) =
          __floats2half2_rn(oacc[mt][nt][0] * inv0, oacc[mt][nt][1] * inv0);
      *reinterpret_cast<__half2*>(O + (r + 8) * DM + c) =
          __floats2half2_rn(oacc[mt][nt][2] * inv1, oacc[mt][nt][3] * inv1);
    }
  }
}

// ---------------- launch ----------------
extern "C" void kernel_launch(void* const* d_in, const int* in_sizes, int n_in,
                              void* d_out, int out_size) {
  const float* x    = (const float*)d_in[0];
  const float* mem  = (const float*)d_in[1];
  const float* ln1a = (const float*)d_in[2];
  const float* ln1b = (const float*)d_in[3];
  const float* ln2a = (const float*)d_in[4];
  const float* ln2b = (const float*)d_in[5];
  const float* ln3a = (const float*)d_in[6];
  const float* ln3b = (const float*)d_in[7];
  const float* a1wq = (const float*)d_in[8];
  const float* a1wk = (const float*)d_in[9];
  const float* a1wv = (const float*)d_in[10];
  const float* a1wo = (const float*)d_in[11];
  const float* a1bo = (const float*)d_in[12];
  const float* a2wq = (const float*)d_in[13];
  const float* a2wk = (const float*)d_in[14];
  const float* a2wv = (const float*)d_in[15];
  const float* a2wo = (const float*)d_in[16];
  const float* a2bo = (const float*)d_in[17];
  const float* fw1  = (const float*)d_in[18];
  const float* fb1  = (const float*)d_in[19];
  const float* fw2  = (const float*)d_in[20];
  const float* fb2  = (const float*)d_in[21];
  float* out = (float*)d_out;

  float* p_res;
  __half *p_ln, *p_mem, *p_q, *p_k, *p_v, *p_att, *p_ffn;
  __half *w0, *w1, *w2, *w3, *w4, *w5, *w6, *w7, *wf1, *wf2;
  cudaGetSymbolAddress((void**)&p_res, g_res);
  cudaGetSymbolAddress((void**)&p_ln,  h_ln);
  cudaGetSymbolAddress((void**)&p_mem, h_mem);
  cudaGetSymbolAddress((void**)&p_q,   h_q);
  cudaGetSymbolAddress((void**)&p_k,   h_k);
  cudaGetSymbolAddress((void**)&p_v,   h_v);
  cudaGetSymbolAddress((void**)&p_att, h_att);
  cudaGetSymbolAddress((void**)&p_ffn, h_ffn);
  cudaGetSymbolAddress((void**)&w0, h_w0);   cudaGetSymbolAddress((void**)&w1, h_w1);
  cudaGetSymbolAddress((void**)&w2, h_w2);   cudaGetSymbolAddress((void**)&w3, h_w3);
  cudaGetSymbolAddress((void**)&w4, h_w4);   cudaGetSymbolAddress((void**)&w5, h_w5);
  cudaGetSymbolAddress((void**)&w6, h_w6);   cudaGetSymbolAddress((void**)&w7, h_w7);
  cudaGetSymbolAddress((void**)&wf1, h_wf1); cudaGetSymbolAddress((void**)&wf2, h_wf2);

  cudaFuncSetAttribute(gemm_h, cudaFuncAttributeMaxDynamicSharedMemorySize, GSMEM);
  cudaFuncSetAttribute(attn_h, cudaFuncAttributeMaxDynamicSharedMemorySize, ASMEM);

  // --- weight / memory conversions ---
  wcvt8_kernel<<<dim3(16, 16, 8), 256>>>(a1wq, a1wk, a1wv, a1wo, a2wq, a2wk, a2wv, a2wo,
                                         w0, w1, w2, w3, w4, w5, w6, w7);
  wcvt_kernel<<<dim3(64, 16), 256>>>(fw1, wf1, DM, DFF);   // [512][2048] -> [2048][512]
  wcvt_kernel<<<dim3(16, 64), 256>>>(fw2, wf2, DFF, DM);   // [2048][512] -> [512][2048]
  cvt_kernel<<<NROWS * DM / 1024, 256>>>(mem, p_mem);

  dim3 gQKV(12, 32);  // 3 weights x 4 col tiles
  dim3 gKV(8, 32);
  dim3 gP(4, 32);
  dim3 gF1(16, 32);
  dim3 gA(16, HEADS, 2);

  // --- self-attention block ---
  ln_kernel<<<NROWS, 256>>>(x, ln1a, ln1b, p_ln);
  gemm_h<<<gQKV, 256, GSMEM>>>(p_ln, w0, w1, w2, nullptr, nullptr,
                               p_q, p_k, p_v, DM, DM, 4, 0, 1);
  attn_h<<<gA, 128, ASMEM>>>(p_q, p_k, p_v, p_att, 1);
  gemm_h<<<gP, 256, GSMEM>>>(p_att, w3, w3, w3, a1bo, x,
                             p_res, p_res, p_res, DM, DM, 4, 0, 0);

  // --- cross-attention block ---
  ln_kernel<<<NROWS, 256>>>(p_res, ln2a, ln2b, p_ln);
  gemm_h<<<gP, 256, GSMEM>>>(p_ln, w4, w4, w4, nullptr, nullptr,
                             p_q, p_q, p_q, DM, DM, 4, 0, 1);
  gemm_h<<<gKV, 256, GSMEM>>>(p_mem, w5, w6, w6, nullptr, nullptr,
                              p_k, p_v, p_v, DM, DM, 4, 0, 1);
  attn_h<<<gA, 128, ASMEM>>>(p_q, p_k, p_v, p_att, 0);
  gemm_h<<<gP, 256, GSMEM>>>(p_att, w7, w7, w7, a2bo, p_res,
                             p_res, p_res, p_res, DM, DM, 4, 0, 0);

  // --- FFN block ---
  ln_kernel<<<NROWS, 256>>>(p_res, ln3a, ln3b, p_ln);
  gemm_h<<<gF1, 256, GSMEM>>>(p_ln, wf1, wf1, wf1, fb1, nullptr,
                              p_ffn, p_ffn, p_ffn, DFF, DM, 16, 1, 1);
  gemm_h<<<gP, 256, GSMEM>>>(p_ffn, wf2, wf2, wf2, fb2, p_res,
                             out, out, out, DM, DFF, 4, 0, 0);
}